// round 16
// baseline (speedup 1.0000x reference)
#include <cuda_runtime.h>
#include <math.h>

#define H 4096
#define INV_SQRT_D (1.0f / 64.0f)
#define NROWS (4 * H + 2)

// ---------------- device scratch (allocation-free) ----------------
__device__ float g_q[H];
__device__ float g_k[H];     // already scaled by 1/sqrt(d)
__device__ float g_v[H];
__device__ float g_opre[H];  // Wo@x + bo (pre-sigmoid)
__device__ float g_dots[2];  // wi.x, wf.x
__device__ float g_inv;      // 1/denom (published by update block 0)
__device__ int   g_flag;     // g_inv ready flag (reset by matvec each replay)

// ---------------- reductions ----------------
__device__ __forceinline__ float warp_reduce(float v) {
    #pragma unroll
    for (int o = 16; o > 0; o >>= 1)
        v += __shfl_down_sync(0xffffffffu, v, o);
    return v;
}

// ---------------- kernel A: all matvecs + scalar-gate dots ----------------
// One WARP per output row; 256-thread blocks (8 warp-rows). Exact R10 form
// (best-measured pairing: matvec+gap = 48.7us).
__global__ void __launch_bounds__(256)
matvec_kernel(const float* __restrict__ x,
              const float* __restrict__ Wq, const float* __restrict__ Wk,
              const float* __restrict__ Wv, const float* __restrict__ Wo,
              const float* __restrict__ bq, const float* __restrict__ bk,
              const float* __restrict__ bv, const float* __restrict__ bo,
              const float* __restrict__ wi, const float* __restrict__ wf) {
    if (blockIdx.x == 0 && threadIdx.x == 0) g_flag = 0;  // reset for this replay

    int gw   = (blockIdx.x * 256 + threadIdx.x) >> 5;  // global warp id = row
    int lane = threadIdx.x & 31;
    if (gw >= NROWS) return;

    const float* wrow;
    if      (gw <     H) wrow = Wq + (size_t) gw          * H;
    else if (gw < 2 * H) wrow = Wk + (size_t)(gw -   H)   * H;
    else if (gw < 3 * H) wrow = Wv + (size_t)(gw - 2*H)   * H;
    else if (gw < 4 * H) wrow = Wo + (size_t)(gw - 3*H)   * H;
    else                 wrow = (gw == 4 * H) ? wi : wf;

    const float4* w4 = (const float4*)wrow;
    const float4* x4 = (const float4*)x;

    float s0 = 0.0f, s1 = 0.0f;
    #pragma unroll 8
    for (int i = 0; i < (H / 4) / 32; i += 2) {   // 32 f4 per lane
        int ia = lane + i * 32;
        int ib = lane + (i + 1) * 32;
        float4 wa = __ldcs(&w4[ia]);
        float4 wb = __ldcs(&w4[ib]);
        float4 xa = x4[ia];
        float4 xb = x4[ib];
        s0 += wa.x * xa.x + wa.y * xa.y + wa.z * xa.z + wa.w * xa.w;
        s1 += wb.x * xb.x + wb.y * xb.y + wb.z * xb.z + wb.w * xb.w;
    }
    float sum = warp_reduce(s0 + s1);

    if (lane == 0) {
        if      (gw <     H) g_q[gw]          = sum + bq[gw];
        else if (gw < 2 * H) g_k[gw -   H]    = (sum + bk[gw - H]) * INV_SQRT_D;
        else if (gw < 3 * H) g_v[gw - 2*H]    = sum + bv[gw - 2*H];
        else if (gw < 4 * H) g_opre[gw - 3*H] = sum + bo[gw - 3*H];
        else                 g_dots[gw - 4*H] = sum;
    }
}

// ---------------- kernel B: C update + n/gates/denom (block 0) + readout ----
// One 256-thread BLOCK per C row. Exact R15 body (measured 23.49us):
// 2-chunk load-batching lengthens same-direction DRAM bursts.
__global__ void __launch_bounds__(256)
update_kernel(const float* __restrict__ C_prev,
              const float* __restrict__ n_prev,
              const float* __restrict__ bi, const float* __restrict__ bf,
              float* __restrict__ out_h, float* __restrict__ out_C,
              float* __restrict__ out_n) {
    __shared__ float red[8];
    int row  = blockIdx.x;
    int tid  = threadIdx.x;
    int lane = tid & 31;
    int wid  = tid >> 5;

    // gate scalars: uniform, cheap
    float ig = expf(g_dots[0] + bi[0]);
    float fg = 1.0f / (1.0f + expf(-(g_dots[1] + bf[0])));

    if (row == 0) {
        // n = fg*n_prev + ig*k ; denom = max(|n.q|,1) ; publish 1/denom
        const float4* k4  = (const float4*)g_k;
        const float4* q4  = (const float4*)g_q;
        const float4* np4 = (const float4*)n_prev;
        float4*       on4 = (float4*)out_n;
        float nd = 0.0f;
        #pragma unroll
        for (int i = 0; i < (H / 4) / 256; i++) {
            int idx = tid + i * 256;
            float4 kk = k4[idx];
            float4 qq = q4[idx];
            float4 np = np4[idx];
            float4 nn;
            nn.x = fg * np.x + ig * kk.x;
            nn.y = fg * np.y + ig * kk.y;
            nn.z = fg * np.z + ig * kk.z;
            nn.w = fg * np.w + ig * kk.w;
            on4[idx] = nn;
            nd += nn.x * qq.x + nn.y * qq.y + nn.z * qq.z + nn.w * qq.w;
        }
        nd = warp_reduce(nd);
        if (lane == 0) red[wid] = nd;
        __syncthreads();
        if (tid == 0) {
            float t = red[0] + red[1] + red[2] + red[3]
                    + red[4] + red[5] + red[6] + red[7];
            g_inv = 1.0f / fmaxf(fabsf(t), 1.0f);
            __threadfence();
            atomicExch(&g_flag, 1);
        }
        __syncthreads();   // red[] reusable below
    }

    // main pass: stream C_prev -> C, fused dot with q.
    // 2 chunks per iter: both loads issued before both stores.
    float ivr = ig * g_v[row];
    const float4* cp4 = (const float4*)(C_prev + (size_t)row * H);
    float4*       co4 = (float4*)      (out_C  + (size_t)row * H);
    const float4* k4  = (const float4*)g_k;
    const float4* q4  = (const float4*)g_q;

    float dot = 0.0f;
    #pragma unroll
    for (int i = 0; i < (H / 4) / 256; i += 2) {   // 2 iters of 2 chunks
        int ia = tid + i * 256;
        int ib = tid + (i + 1) * 256;
        float4 ca = __ldcs(&cp4[ia]);
        float4 cb = __ldcs(&cp4[ib]);
        float4 ka = k4[ia];
        float4 kb = k4[ib];
        float4 na, nb;
        na.x = fg * ca.x + ivr * ka.x;
        na.y = fg * ca.y + ivr * ka.y;
        na.z = fg * ca.z + ivr * ka.z;
        na.w = fg * ca.w + ivr * ka.w;
        nb.x = fg * cb.x + ivr * kb.x;
        nb.y = fg * cb.y + ivr * kb.y;
        nb.z = fg * cb.z + ivr * kb.z;
        nb.w = fg * cb.w + ivr * kb.w;
        __stcs(&co4[ia], na);
        __stcs(&co4[ib], nb);
        float4 qa = q4[ia];
        float4 qb = q4[ib];
        dot += na.x * qa.x + na.y * qa.y + na.z * qa.z + na.w * qa.w;
        dot += nb.x * qb.x + nb.y * qb.y + nb.z * qb.z + nb.w * qb.w;
    }
    dot = warp_reduce(dot);
    if (lane == 0) red[wid] = dot;
    __syncthreads();
    if (tid == 0) {
        float t = red[0] + red[1] + red[2] + red[3]
                + red[4] + red[5] + red[6] + red[7];
        while (*(volatile int*)&g_flag == 0) __nanosleep(40);
        float invden = *(volatile float*)&g_inv;
        float h_tilde = t * invden;
        float o = 1.0f / (1.0f + expf(-g_opre[row]));
        out_h[row] = o * h_tilde;
    }
}

// ---------------- launcher ----------------
extern "C" void kernel_launch(void* const* d_in, const int* in_sizes, int n_in,
                              void* d_out, int out_size) {
    const float* x      = (const float*)d_in[0];
    // d_in[1] = h_prev (unused by mLSTM math)
    const float* C_prev = (const float*)d_in[2];
    const float* n_prev = (const float*)d_in[3];
    const float* Wq     = (const float*)d_in[4];
    const float* Wk     = (const float*)d_in[5];
    const float* Wv     = (const float*)d_in[6];
    const float* Wo     = (const float*)d_in[7];
    const float* bq     = (const float*)d_in[8];
    const float* bk     = (const float*)d_in[9];
    const float* bv     = (const float*)d_in[10];
    const float* bo     = (const float*)d_in[11];
    const float* wi     = (const float*)d_in[12];
    const float* bi     = (const float*)d_in[13];
    const float* wf     = (const float*)d_in[14];
    const float* bf     = (const float*)d_in[15];

    float* out   = (float*)d_out;
    float* out_h = out;                      // [H]
    float* out_C = out + H;                  // [H, H]
    float* out_n = out + H + (size_t)H * H;  // [H]

    int mv_blocks = (NROWS + 7) / 8;         // 8 warp-rows per 256-thread block
    matvec_kernel<<<mv_blocks, 256>>>(x, Wq, Wk, Wv, Wo, bq, bk, bv, bo, wi, wf);
    update_kernel<<<H, 256>>>(C_prev, n_prev, bi, bf, out_h, out_C, out_n);
}

// round 17
// speedup vs baseline: 1.0224x; 1.0224x over previous
#include <cuda_runtime.h>
#include <math.h>

#define H 4096
#define INV_SQRT_D (1.0f / 64.0f)
#define NROWS (4 * H + 2)

// ---------------- device scratch (allocation-free) ----------------
__device__ float g_q[H];
__device__ float g_k[H];     // already scaled by 1/sqrt(d)
__device__ float g_v[H];
__device__ float g_opre[H];  // Wo@x + bo (pre-sigmoid)
__device__ float g_dots[2];  // wi.x, wf.x
__device__ float g_inv;      // 1/denom (published by update block 0)
__device__ int   g_flag;     // g_inv ready flag (reset by matvec each replay)

// ---------------- reductions ----------------
__device__ __forceinline__ float warp_reduce(float v) {
    #pragma unroll
    for (int o = 16; o > 0; o >>= 1)
        v += __shfl_down_sync(0xffffffffu, v, o);
    return v;
}

// ---------------- kernel A: all matvecs + scalar-gate dots ----------------
// One WARP per output row; 256-thread blocks (8 warp-rows). R10-proven form.
__global__ void __launch_bounds__(256)
matvec_kernel(const float* __restrict__ x,
              const float* __restrict__ Wq, const float* __restrict__ Wk,
              const float* __restrict__ Wv, const float* __restrict__ Wo,
              const float* __restrict__ bq, const float* __restrict__ bk,
              const float* __restrict__ bv, const float* __restrict__ bo,
              const float* __restrict__ wi, const float* __restrict__ wf) {
    if (blockIdx.x == 0 && threadIdx.x == 0) g_flag = 0;  // reset for this replay

    int gw   = (blockIdx.x * 256 + threadIdx.x) >> 5;  // global warp id = row
    int lane = threadIdx.x & 31;
    if (gw >= NROWS) return;

    const float* wrow;
    if      (gw <     H) wrow = Wq + (size_t) gw          * H;
    else if (gw < 2 * H) wrow = Wk + (size_t)(gw -   H)   * H;
    else if (gw < 3 * H) wrow = Wv + (size_t)(gw - 2*H)   * H;
    else if (gw < 4 * H) wrow = Wo + (size_t)(gw - 3*H)   * H;
    else                 wrow = (gw == 4 * H) ? wi : wf;

    const float4* w4 = (const float4*)wrow;
    const float4* x4 = (const float4*)x;

    float s0 = 0.0f, s1 = 0.0f;
    #pragma unroll 8
    for (int i = 0; i < (H / 4) / 32; i += 2) {   // 32 f4 per lane
        int ia = lane + i * 32;
        int ib = lane + (i + 1) * 32;
        float4 wa = __ldcs(&w4[ia]);
        float4 wb = __ldcs(&w4[ib]);
        float4 xa = x4[ia];
        float4 xb = x4[ib];
        s0 += wa.x * xa.x + wa.y * xa.y + wa.z * xa.z + wa.w * xa.w;
        s1 += wb.x * xb.x + wb.y * xb.y + wb.z * xb.z + wb.w * xb.w;
    }
    float sum = warp_reduce(s0 + s1);

    if (lane == 0) {
        if      (gw <     H) g_q[gw]          = sum + bq[gw];
        else if (gw < 2 * H) g_k[gw -   H]    = (sum + bk[gw - H]) * INV_SQRT_D;
        else if (gw < 3 * H) g_v[gw - 2*H]    = sum + bv[gw - 2*H];
        else if (gw < 4 * H) g_opre[gw - 3*H] = sum + bo[gw - 3*H];
        else                 g_dots[gw - 4*H] = sum;
    }
}

// ---------------- kernel B: C update + n/gates/denom (block 0) + readout ----
// One 256-thread BLOCK per C row. FULL 4-chunk batching: all 4 C_prev loads
// issued back-to-back, then compute, then all 4 stores back-to-back — one
// read burst + one write burst per row, minimizing DRAM R/W turnaround.
__global__ void __launch_bounds__(256)
update_kernel(const float* __restrict__ C_prev,
              const float* __restrict__ n_prev,
              const float* __restrict__ bi, const float* __restrict__ bf,
              float* __restrict__ out_h, float* __restrict__ out_C,
              float* __restrict__ out_n) {
    __shared__ float red[8];
    int row  = blockIdx.x;
    int tid  = threadIdx.x;
    int lane = tid & 31;
    int wid  = tid >> 5;

    // gate scalars: uniform, cheap
    float ig = expf(g_dots[0] + bi[0]);
    float fg = 1.0f / (1.0f + expf(-(g_dots[1] + bf[0])));

    if (row == 0) {
        // n = fg*n_prev + ig*k ; denom = max(|n.q|,1) ; publish 1/denom
        const float4* k4  = (const float4*)g_k;
        const float4* q4  = (const float4*)g_q;
        const float4* np4 = (const float4*)n_prev;
        float4*       on4 = (float4*)out_n;
        float nd = 0.0f;
        #pragma unroll
        for (int i = 0; i < (H / 4) / 256; i++) {
            int idx = tid + i * 256;
            float4 kk = k4[idx];
            float4 qq = q4[idx];
            float4 np = np4[idx];
            float4 nn;
            nn.x = fg * np.x + ig * kk.x;
            nn.y = fg * np.y + ig * kk.y;
            nn.z = fg * np.z + ig * kk.z;
            nn.w = fg * np.w + ig * kk.w;
            on4[idx] = nn;
            nd += nn.x * qq.x + nn.y * qq.y + nn.z * qq.z + nn.w * qq.w;
        }
        nd = warp_reduce(nd);
        if (lane == 0) red[wid] = nd;
        __syncthreads();
        if (tid == 0) {
            float t = red[0] + red[1] + red[2] + red[3]
                    + red[4] + red[5] + red[6] + red[7];
            g_inv = 1.0f / fmaxf(fabsf(t), 1.0f);
            __threadfence();
            atomicExch(&g_flag, 1);
        }
        __syncthreads();   // red[] reusable below
    }

    // main pass: one read burst, compute, one write burst, then q-dot.
    float ivr = ig * g_v[row];
    const float4* cp4 = (const float4*)(C_prev + (size_t)row * H);
    float4*       co4 = (float4*)      (out_C  + (size_t)row * H);
    const float4* k4  = (const float4*)g_k;
    const float4* q4  = (const float4*)g_q;

    int i0 = tid, i1 = tid + 256, i2 = tid + 512, i3 = tid + 768;

    // read burst (4 back-to-back streaming loads)
    float4 c0 = __ldcs(&cp4[i0]);
    float4 c1 = __ldcs(&cp4[i1]);
    float4 c2 = __ldcs(&cp4[i2]);
    float4 c3 = __ldcs(&cp4[i3]);
    float4 k0 = k4[i0], k1 = k4[i1], k2 = k4[i2], k3 = k4[i3];

    // compute in place
    c0.x = fg * c0.x + ivr * k0.x;  c0.y = fg * c0.y + ivr * k0.y;
    c0.z = fg * c0.z + ivr * k0.z;  c0.w = fg * c0.w + ivr * k0.w;
    c1.x = fg * c1.x + ivr * k1.x;  c1.y = fg * c1.y + ivr * k1.y;
    c1.z = fg * c1.z + ivr * k1.z;  c1.w = fg * c1.w + ivr * k1.w;
    c2.x = fg * c2.x + ivr * k2.x;  c2.y = fg * c2.y + ivr * k2.y;
    c2.z = fg * c2.z + ivr * k2.z;  c2.w = fg * c2.w + ivr * k2.w;
    c3.x = fg * c3.x + ivr * k3.x;  c3.y = fg * c3.y + ivr * k3.y;
    c3.z = fg * c3.z + ivr * k3.z;  c3.w = fg * c3.w + ivr * k3.w;

    // write burst (4 back-to-back streaming stores)
    __stcs(&co4[i0], c0);
    __stcs(&co4[i1], c1);
    __stcs(&co4[i2], c2);
    __stcs(&co4[i3], c3);

    // q-dot (L2/L1-hot loads, after the bursts)
    float4 q0 = q4[i0], q1 = q4[i1], q2 = q4[i2], q3 = q4[i3];
    float dot = c0.x * q0.x + c0.y * q0.y + c0.z * q0.z + c0.w * q0.w
              + c1.x * q1.x + c1.y * q1.y + c1.z * q1.z + c1.w * q1.w
              + c2.x * q2.x + c2.y * q2.y + c2.z * q2.z + c2.w * q2.w
              + c3.x * q3.x + c3.y * q3.y + c3.z * q3.z + c3.w * q3.w;

    dot = warp_reduce(dot);
    if (lane == 0) red[wid] = dot;
    __syncthreads();
    if (tid == 0) {
        float t = red[0] + red[1] + red[2] + red[3]
                + red[4] + red[5] + red[6] + red[7];
        while (*(volatile int*)&g_flag == 0) __nanosleep(40);
        float invden = *(volatile float*)&g_inv;
        float h_tilde = t * invden;
        float o = 1.0f / (1.0f + expf(-g_opre[row]));
        out_h[row] = o * h_tilde;
    }
}

// ---------------- launcher ----------------
extern "C" void kernel_launch(void* const* d_in, const int* in_sizes, int n_in,
                              void* d_out, int out_size) {
    const float* x      = (const float*)d_in[0];
    // d_in[1] = h_prev (unused by mLSTM math)
    const float* C_prev = (const float*)d_in[2];
    const float* n_prev = (const float*)d_in[3];
    const float* Wq     = (const float*)d_in[4];
    const float* Wk     = (const float*)d_in[5];
    const float* Wv     = (const float*)d_in[6];
    const float* Wo     = (const float*)d_in[7];
    const float* bq     = (const float*)d_in[8];
    const float* bk     = (const float*)d_in[9];
    const float* bv     = (const float*)d_in[10];
    const float* bo     = (const float*)d_in[11];
    const float* wi     = (const float*)d_in[12];
    const float* bi     = (const float*)d_in[13];
    const float* wf     = (const float*)d_in[14];
    const float* bf     = (const float*)d_in[15];

    float* out   = (float*)d_out;
    float* out_h = out;                      // [H]
    float* out_C = out + H;                  // [H, H]
    float* out_n = out + H + (size_t)H * H;  // [H]

    int mv_blocks = (NROWS + 7) / 8;         // 8 warp-rows per 256-thread block
    matvec_kernel<<<mv_blocks, 256>>>(x, Wq, Wk, Wv, Wo, bq, bk, bv, bo, wi, wf);
    update_kernel<<<H, 256>>>(C_prev, n_prev, bi, bf, out_h, out_C, out_n);
}